// round 9
// baseline (speedup 1.0000x reference)
#include <cuda_runtime.h>
#include <cstdint>

// ---------------------------------------------------------------------------
// SSA (spiking self-attention) — B=32, C=512, N=1024
// Pipeline:
//   y_{q,k,v} = W @ x            (fp32 SIMT GEMM, per batch)
//   per-channel mean/var over (B,N)  -> BN -> LIF threshold (binary spikes)
//   kv[c,d]   = sum_n k[c,n] v[d,n]  (bitpacked AND+POPC, exact)
//   attn[d,n] = sum_c q[c,n] kv[c,d] (fp32 GEMM, exact integers) -> spike
//   proj      = Wp @ attn + bias     (fp32 GEMM)
//   stats -> BN -> LIF -> d_out
// ---------------------------------------------------------------------------

namespace {
constexpr int  BB  = 32;
constexpr int  CC  = 512;
constexpr int  NN  = 1024;
constexpr long BCN = (long)BB * CC * NN;   // 16,777,216
constexpr float TAUf = 1.1f;
constexpr float EPSf = 1e-5f;
}

// scratch (device globals: no allocation allowed)
__device__ float    g_y[3][BB * CC * NN];      // conv outputs q,k,v
__device__ float    g_sq[BB * CC * NN];        // q spikes (float 0/1)
__device__ unsigned g_kbits[BB * CC * NN / 32];
__device__ unsigned g_vbits[BB * CC * NN / 32];
__device__ float    g_kv[BB * CC * CC];        // kv counts (exact ints as fp32)
__device__ float    g_attn[BB * CC * NN];      // attn spikes (float 0/1)
__device__ float    g_proj[BB * CC * NN];      // proj conv output
__device__ float    g_mean[4 * CC];
__device__ float    g_inv[4 * CC];

// ---------------------------------------------------------------------------
// Generic tiled GEMM: C[m,n] = sum_k Aop[m,k] * B[k,n]  (+ epilogue)
//   AROW=true : Aop[m,k] = A[m*K + k]   (row-major weights)
//   AROW=false: Aop[m,k] = A[k*M + m]   (transposed access, used for kv^T)
//   EPI: 0 = raw, 1 = +bias[m], 2 = attn spike (acc*0.125/1.1 - 0.5 >= 0)
// Tiles: 128x128x16, 256 threads, 8x8 per thread.
// ---------------------------------------------------------------------------
template<bool AROW, int EPI>
__global__ void __launch_bounds__(256)
gemm_kernel(const float* __restrict__ A, long strideA,
            const float* __restrict__ Bm, long strideB,
            float* __restrict__ Cm, long strideC,
            int M, int Nn, int K,
            const float* __restrict__ bias)
{
    __shared__ float As[16][129];   // +1 pad: conflict-free column writes
    __shared__ float Bs[16][128];

    const int bz = blockIdx.z;
    const float* Ab = A + (long)bz * strideA;
    const float* Bb = Bm + (long)bz * strideB;
    float* Cb = Cm + (long)bz * strideC;

    const int m0 = blockIdx.y * 128;
    const int n0 = blockIdx.x * 128;
    const int tid = threadIdx.x;
    const int tx = tid & 15;        // n direction
    const int ty = tid >> 4;        // m direction

    float acc[8][8];
#pragma unroll
    for (int i = 0; i < 8; i++)
#pragma unroll
        for (int j = 0; j < 8; j++) acc[i][j] = 0.f;

    for (int k0 = 0; k0 < K; k0 += 16) {
        if (AROW) {
#pragma unroll
            for (int i = 0; i < 8; i++) {
                int idx = tid + i * 256;
                int k = idx & 15;
                int m = idx >> 4;
                As[k][m] = Ab[(long)(m0 + m) * K + (k0 + k)];
            }
        } else {
#pragma unroll
            for (int i = 0; i < 8; i++) {
                int idx = tid + i * 256;
                int m = idx & 127;
                int k = idx >> 7;
                As[k][m] = Ab[(long)(k0 + k) * M + (m0 + m)];
            }
        }
#pragma unroll
        for (int i = 0; i < 8; i++) {
            int idx = tid + i * 256;
            int n = idx & 127;
            int k = idx >> 7;
            Bs[k][n] = Bb[(long)(k0 + k) * Nn + (n0 + n)];
        }
        __syncthreads();

#pragma unroll
        for (int kk = 0; kk < 16; kk++) {
            float ar[8], br[8];
#pragma unroll
            for (int i = 0; i < 8; i++) ar[i] = As[kk][ty * 8 + i];
            float4 b0 = *(const float4*)&Bs[kk][tx * 8];
            float4 b1 = *(const float4*)&Bs[kk][tx * 8 + 4];
            br[0] = b0.x; br[1] = b0.y; br[2] = b0.z; br[3] = b0.w;
            br[4] = b1.x; br[5] = b1.y; br[6] = b1.z; br[7] = b1.w;
#pragma unroll
            for (int i = 0; i < 8; i++)
#pragma unroll
                for (int j = 0; j < 8; j++)
                    acc[i][j] = fmaf(ar[i], br[j], acc[i][j]);
        }
        __syncthreads();
    }

#pragma unroll
    for (int i = 0; i < 8; i++) {
        int row = m0 + ty * 8 + i;
        float bv = (EPI == 1) ? bias[row] : 0.f;
        float tmp[8];
#pragma unroll
        for (int j = 0; j < 8; j++) {
            float v = acc[i][j];
            if (EPI == 1) v += bv;
            if (EPI == 2) v = ((v * 0.125f) / TAUf - 0.5f >= 0.f) ? 1.f : 0.f;
            tmp[j] = v;
        }
        float4 o0 = make_float4(tmp[0], tmp[1], tmp[2], tmp[3]);
        float4 o1 = make_float4(tmp[4], tmp[5], tmp[6], tmp[7]);
        *(float4*)&Cb[(long)row * Nn + n0 + tx * 8] = o0;
        *(float4*)&Cb[(long)row * Nn + n0 + tx * 8 + 4] = o1;
    }
}

// ---------------------------------------------------------------------------
// Per-channel mean / inv-std over (B, N): one block per channel.
// ---------------------------------------------------------------------------
__global__ void __launch_bounds__(256)
stats_kernel(const float* __restrict__ y,
             float* __restrict__ mean_out, float* __restrict__ inv_out)
{
    const int c = blockIdx.x;
    const int tid = threadIdx.x;
    float s = 0.f, s2 = 0.f;
    for (int b = 0; b < BB; b++) {
        const float* p = y + (long)b * CC * NN + (long)c * NN;
        for (int n = tid; n < NN; n += 256) {
            float v = p[n];
            s += v;
            s2 = fmaf(v, v, s2);
        }
    }
    __shared__ float sh1[8], sh2[8];
#pragma unroll
    for (int o = 16; o > 0; o >>= 1) {
        s  += __shfl_down_sync(0xffffffffu, s,  o);
        s2 += __shfl_down_sync(0xffffffffu, s2, o);
    }
    if ((tid & 31) == 0) { sh1[tid >> 5] = s; sh2[tid >> 5] = s2; }
    __syncthreads();
    if (tid < 32) {
        s  = (tid < 8) ? sh1[tid] : 0.f;
        s2 = (tid < 8) ? sh2[tid] : 0.f;
#pragma unroll
        for (int o = 4; o > 0; o >>= 1) {
            s  += __shfl_down_sync(0xffffffffu, s,  o);
            s2 += __shfl_down_sync(0xffffffffu, s2, o);
        }
        if (tid == 0) {
            const float invn = 1.f / (float)(BB * NN);
            float m = s * invn;
            float var = s2 * invn - m * m;
            mean_out[c] = m;
            inv_out[c] = rsqrtf(var + EPSf);
        }
    }
}

// ---------------------------------------------------------------------------
// BN + LIF threshold -> float spikes (used for q spikes and final output)
// ---------------------------------------------------------------------------
__global__ void __launch_bounds__(256)
spike_float_kernel(const float* __restrict__ y,
                   const float* __restrict__ mean, const float* __restrict__ inv,
                   const float* __restrict__ gamma, const float* __restrict__ beta,
                   float* __restrict__ out, float vth)
{
    long i = (long)blockIdx.x * 256 + threadIdx.x;
    int c = (int)((i >> 10) & (CC - 1));     // N = 1024
    float bnv = fmaf(gamma[c] * inv[c], y[i] - mean[c], beta[c]);
    float u = bnv / TAUf - vth;
    out[i] = (u >= 0.f) ? 1.f : 0.f;
}

// ---------------------------------------------------------------------------
// BN + LIF threshold -> bitpacked spikes (k, v)
// ---------------------------------------------------------------------------
__global__ void __launch_bounds__(256)
spike_pack_kernel(const float* __restrict__ y,
                  const float* __restrict__ mean, const float* __restrict__ inv,
                  const float* __restrict__ gamma, const float* __restrict__ beta,
                  unsigned* __restrict__ bits)
{
    long i = (long)blockIdx.x * 256 + threadIdx.x;
    int c = (int)((i >> 10) & (CC - 1));
    float bnv = fmaf(gamma[c] * inv[c], y[i] - mean[c], beta[c]);
    bool spike = (bnv / TAUf - 1.0f) >= 0.f;
    unsigned m = __ballot_sync(0xffffffffu, spike);
    if ((threadIdx.x & 31) == 0) bits[i >> 5] = m;
}

// ---------------------------------------------------------------------------
// kv[b,c,d] = popcount over N of k_bits & v_bits  (exact integer, as fp32)
// 64x64 output tile per block, 4x4 per thread, 32 words of N-bits.
// ---------------------------------------------------------------------------
__global__ void __launch_bounds__(256)
kv_popc_kernel(const unsigned* __restrict__ kb, const unsigned* __restrict__ vb,
               float* __restrict__ kv)
{
    __shared__ unsigned ks[32][65];   // [word][row], +1 pad
    __shared__ unsigned vs[32][65];
    const int bz = blockIdx.z;
    const int c0 = blockIdx.y * 64;
    const int d0 = blockIdx.x * 64;
    const unsigned* kbb = kb + (long)bz * CC * (NN / 32);
    const unsigned* vbb = vb + (long)bz * CC * (NN / 32);
    const int tid = threadIdx.x;
#pragma unroll
    for (int it = 0; it < 8; it++) {
        int idx = tid + it * 256;
        int r = idx >> 5;
        int w = idx & 31;
        ks[w][r] = kbb[(long)(c0 + r) * 32 + w];
        vs[w][r] = vbb[(long)(d0 + r) * 32 + w];
    }
    __syncthreads();
    const int tm = (tid >> 4) * 4;
    const int tn = (tid & 15) * 4;
    int cnt[4][4];
#pragma unroll
    for (int i = 0; i < 4; i++)
#pragma unroll
        for (int j = 0; j < 4; j++) cnt[i][j] = 0;
#pragma unroll
    for (int w = 0; w < 32; w++) {
        unsigned a[4], b[4];
#pragma unroll
        for (int i = 0; i < 4; i++) a[i] = ks[w][tm + i];
#pragma unroll
        for (int j = 0; j < 4; j++) b[j] = vs[w][tn + j];
#pragma unroll
        for (int i = 0; i < 4; i++)
#pragma unroll
            for (int j = 0; j < 4; j++)
                cnt[i][j] += __popc(a[i] & b[j]);
    }
    float* kvb = kv + (long)bz * CC * CC;
#pragma unroll
    for (int i = 0; i < 4; i++)
#pragma unroll
        for (int j = 0; j < 4; j++)
            kvb[(long)(c0 + tm + i) * CC + (d0 + tn + j)] = (float)cnt[i][j];
}

// ---------------------------------------------------------------------------
extern "C" void kernel_launch(void* const* d_in, const int* in_sizes, int n_in,
                              void* d_out, int out_size)
{
    const float* x      = (const float*)d_in[0];
    const float* q_w    = (const float*)d_in[1];
    const float* q_g    = (const float*)d_in[2];
    const float* q_b    = (const float*)d_in[3];
    const float* k_w    = (const float*)d_in[4];
    const float* k_g    = (const float*)d_in[5];
    const float* k_b    = (const float*)d_in[6];
    const float* v_w    = (const float*)d_in[7];
    const float* v_g    = (const float*)d_in[8];
    const float* v_b    = (const float*)d_in[9];
    const float* p_w    = (const float*)d_in[10];
    const float* p_g    = (const float*)d_in[11];   // proj_gamma
    const float* p_beta = (const float*)d_in[12];   // proj_beta
    const float* p_bias = (const float*)d_in[13];   // proj_b

    void* p;
    cudaGetSymbolAddress(&p, g_y);     float*    gy     = (float*)p;
    cudaGetSymbolAddress(&p, g_sq);    float*    gsq    = (float*)p;
    cudaGetSymbolAddress(&p, g_kbits); unsigned* gkbits = (unsigned*)p;
    cudaGetSymbolAddress(&p, g_vbits); unsigned* gvbits = (unsigned*)p;
    cudaGetSymbolAddress(&p, g_kv);    float*    gkv    = (float*)p;
    cudaGetSymbolAddress(&p, g_attn);  float*    gattn  = (float*)p;
    cudaGetSymbolAddress(&p, g_proj);  float*    gproj  = (float*)p;
    cudaGetSymbolAddress(&p, g_mean);  float*    gmean  = (float*)p;
    cudaGetSymbolAddress(&p, g_inv);   float*    ginv   = (float*)p;

    float* yq = gy;
    float* yk = gy + BCN;
    float* yv = gy + 2 * BCN;

    const long sBN = (long)CC * NN;   // per-batch stride of [C,N] tensors

    dim3 gemmGrid(NN / 128, CC / 128, BB);   // (8, 4, 32)

    // 1) conv1x1 for q, k, v
    gemm_kernel<true, 0><<<gemmGrid, 256>>>(q_w, 0, x, sBN, yq, sBN, CC, NN, CC, nullptr);
    gemm_kernel<true, 0><<<gemmGrid, 256>>>(k_w, 0, x, sBN, yk, sBN, CC, NN, CC, nullptr);
    gemm_kernel<true, 0><<<gemmGrid, 256>>>(v_w, 0, x, sBN, yv, sBN, CC, NN, CC, nullptr);

    // 2) BN stats
    stats_kernel<<<CC, 256>>>(yq, gmean + 0 * CC, ginv + 0 * CC);
    stats_kernel<<<CC, 256>>>(yk, gmean + 1 * CC, ginv + 1 * CC);
    stats_kernel<<<CC, 256>>>(yv, gmean + 2 * CC, ginv + 2 * CC);

    // 3) spikes: q -> float, k/v -> bitpacked
    const unsigned nblk = (unsigned)(BCN / 256);
    spike_float_kernel<<<nblk, 256>>>(yq, gmean + 0 * CC, ginv + 0 * CC, q_g, q_b, gsq, 1.0f);
    spike_pack_kernel<<<nblk, 256>>>(yk, gmean + 1 * CC, ginv + 1 * CC, k_g, k_b, gkbits);
    spike_pack_kernel<<<nblk, 256>>>(yv, gmean + 2 * CC, ginv + 2 * CC, v_g, v_b, gvbits);

    // 4) kv = k @ v^T via popcount
    dim3 kvGrid(CC / 64, CC / 64, BB);       // (8, 8, 32)
    kv_popc_kernel<<<kvGrid, 256>>>(gkbits, gvbits, gkv);

    // 5) attn[d,n] = sum_c q[c,n] * kv[c,d]  -> spike epilogue
    gemm_kernel<false, 2><<<gemmGrid, 256>>>(gkv, (long)CC * CC, gsq, sBN,
                                             gattn, sBN, CC, NN, CC, nullptr);

    // 6) proj conv + bias
    gemm_kernel<true, 1><<<gemmGrid, 256>>>(p_w, 0, gattn, sBN, gproj, sBN,
                                            CC, NN, CC, p_bias);

    // 7) final BN stats + spike -> d_out
    stats_kernel<<<CC, 256>>>(gproj, gmean + 3 * CC, ginv + 3 * CC);
    spike_float_kernel<<<nblk, 256>>>(gproj, gmean + 3 * CC, ginv + 3 * CC,
                                      p_g, p_beta, (float*)d_out, 1.0f);
}

// round 10
// speedup vs baseline: 4.4119x; 4.4119x over previous
#include <cuda_runtime.h>
#include <cuda_bf16.h>
#include <cuda_fp16.h>
#include <cstdint>

// ---------------------------------------------------------------------------
// SSA — B=32, C=512, N=1024. Tensor-core (mma.sync) version.
//   qkv conv : one bf16 GEMM, M=1536 (stacked weights), B = x^T
//   stats/BN/LIF; k,v bitpacked; kv via AND+POPC (exact) -> fp16 kv^T
//   attn     : fp16 GEMM (exact integers) + fused spike epilogue
//   proj     : bf16 GEMM with 3-way weight split (fp32-accurate), K=1536
//   stats/BN/LIF -> d_out
// ---------------------------------------------------------------------------

namespace {
constexpr int  BB  = 32;
constexpr int  CC  = 512;
constexpr int  NN  = 1024;
constexpr long BCN = (long)BB * CC * NN;
constexpr float TAUf = 1.1f;
constexpr float EPSf = 1e-5f;
}

// scratch
__device__ float          g_y[(long)BB * 3 * CC * NN];   // qkv conv out fp32
__device__ __nv_bfloat16  g_xT[BCN];                     // x^T  [b][n][c]
__device__ __half         g_qT[BCN];                     // q spikes^T [b][n][c]
__device__ unsigned       g_kbits[BCN / 32];
__device__ unsigned       g_vbits[BCN / 32];
__device__ __half         g_kvT[(long)BB * CC * CC];     // kv^T [b][d][c]
__device__ __nv_bfloat16  g_attn[BCN];                   // attn spikes [b][d][n]
__device__ __nv_bfloat16  g_attnT[BCN];                  // [b][n][d]
__device__ float          g_proj[BCN];
__device__ __nv_bfloat16  g_wqkv[3 * CC * CC];           // stacked q,k,v weights
__device__ __nv_bfloat16  g_pw3[(long)CC * 3 * CC];      // [o][1536]: hi|mid|lo
__device__ float          g_mean[4 * CC];
__device__ float          g_inv[4 * CC];

// ---------------------------------------------------------------------------
__device__ __forceinline__ uint32_t smem_u32(const void* p) {
    return (uint32_t)__cvta_generic_to_shared(p);
}
__device__ __forceinline__ void cp_async16(uint32_t s, const void* g) {
    asm volatile("cp.async.cg.shared.global [%0], [%1], 16;" :: "r"(s), "l"(g));
}
__device__ __forceinline__ void ldm_x4(uint32_t& r0, uint32_t& r1,
                                       uint32_t& r2, uint32_t& r3, uint32_t a) {
    asm volatile("ldmatrix.sync.aligned.m8n8.x4.shared.b16 {%0,%1,%2,%3}, [%4];"
                 : "=r"(r0), "=r"(r1), "=r"(r2), "=r"(r3) : "r"(a));
}
template<int FT>
__device__ __forceinline__ void mma_16816(float* c, const uint32_t* a, const uint32_t* b) {
    if constexpr (FT == 0) {
        asm volatile(
            "mma.sync.aligned.m16n8k16.row.col.f32.bf16.bf16.f32 "
            "{%0,%1,%2,%3},{%4,%5,%6,%7},{%8,%9},{%0,%1,%2,%3};"
            : "+f"(c[0]), "+f"(c[1]), "+f"(c[2]), "+f"(c[3])
            : "r"(a[0]), "r"(a[1]), "r"(a[2]), "r"(a[3]), "r"(b[0]), "r"(b[1]));
    } else {
        asm volatile(
            "mma.sync.aligned.m16n8k16.row.col.f32.f16.f16.f32 "
            "{%0,%1,%2,%3},{%4,%5,%6,%7},{%8,%9},{%0,%1,%2,%3};"
            : "+f"(c[0]), "+f"(c[1]), "+f"(c[2]), "+f"(c[3])
            : "r"(a[0]), "r"(a[1]), "r"(a[2]), "r"(a[3]), "r"(b[0]), "r"(b[1]));
    }
}

// ---------------------------------------------------------------------------
// GEMM: C[m,n] = sum_k A[m][k] * BT[n][k % Kb]
//   A: 16-bit row-major [M][K] (lda), batch stride sA
//   BT: 16-bit row-major [N][Kb] (ldb), batch stride sB
//   FT: 0 bf16, 1 fp16.  EPI: 0 raw f32, 1 +bias f32, 2 attn-spike bf16
// CTA tile 128x128, K-step 32, 8 warps (64x32 per warp), double-buffered.
// ---------------------------------------------------------------------------
template<int FT, int EPI>
__global__ void __launch_bounds__(256)
gemm_mma(const uint16_t* __restrict__ A, int lda, long sA,
         const uint16_t* __restrict__ BT, int ldb, long sB, int Kb,
         void* __restrict__ Cout, int ldc, long sC,
         int M, int Nn, int K, const float* __restrict__ bias)
{
    constexpr int LDS = 40;
    __shared__ uint16_t As[2][128 * LDS];
    __shared__ uint16_t Bs[2][128 * LDS];

    const int bz = blockIdx.z;
    const uint16_t* Ab = A + (long)bz * sA;
    const uint16_t* Bb = BT + (long)bz * sB;
    const int m0 = blockIdx.y * 128, n0 = blockIdx.x * 128;
    const int tid = threadIdx.x;
    const int lane = tid & 31, warp = tid >> 5;
    const int wm = (warp & 1) * 64, wn = (warp >> 1) * 32;

    float acc[4][4][4];
#pragma unroll
    for (int i = 0; i < 4; i++)
#pragma unroll
        for (int j = 0; j < 4; j++)
#pragma unroll
            for (int r = 0; r < 4; r++) acc[i][j][r] = 0.f;

    auto issue = [&](int st, int k0) {
        int kb0 = k0 % Kb;
#pragma unroll
        for (int i = 0; i < 2; i++) {
            int c = tid + i * 256;          // 0..511
            int row = c >> 2, kc = (c & 3) << 3;
            cp_async16(smem_u32(&As[st][row * LDS + kc]),
                       Ab + (long)(m0 + row) * lda + k0 + kc);
            cp_async16(smem_u32(&Bs[st][row * LDS + kc]),
                       Bb + (long)(n0 + row) * ldb + kb0 + kc);
        }
        asm volatile("cp.async.commit_group;");
    };

    const int KT = K / 32;
    issue(0, 0);
    for (int kt = 0; kt < KT; kt++) {
        if (kt + 1 < KT) {
            issue((kt + 1) & 1, (kt + 1) * 32);
            asm volatile("cp.async.wait_group 1;");
        } else {
            asm volatile("cp.async.wait_group 0;");
        }
        __syncthreads();
        const uint16_t* as = As[kt & 1];
        const uint16_t* bs = Bs[kt & 1];
#pragma unroll
        for (int kk = 0; kk < 2; kk++) {
            uint32_t af[4][4], bf[4][2];
#pragma unroll
            for (int mt = 0; mt < 4; mt++) {
                int row = wm + mt * 16 + (lane & 15);
                int kcol = kk * 16 + (lane >> 4) * 8;
                ldm_x4(af[mt][0], af[mt][1], af[mt][2], af[mt][3],
                       smem_u32(&as[row * LDS + kcol]));
            }
#pragma unroll
            for (int p = 0; p < 2; p++) {
                int g = lane >> 3;
                int row = wn + p * 16 + (g >> 1) * 8 + (lane & 7);
                int kcol = kk * 16 + (g & 1) * 8;
                uint32_t r0, r1, r2, r3;
                ldm_x4(r0, r1, r2, r3, smem_u32(&bs[row * LDS + kcol]));
                bf[p * 2][0] = r0; bf[p * 2][1] = r1;
                bf[p * 2 + 1][0] = r2; bf[p * 2 + 1][1] = r3;
            }
#pragma unroll
            for (int mt = 0; mt < 4; mt++)
#pragma unroll
                for (int nt = 0; nt < 4; nt++)
                    mma_16816<FT>(acc[mt][nt], af[mt], bf[nt]);
        }
        __syncthreads();
    }

    // epilogue
#pragma unroll
    for (int mt = 0; mt < 4; mt++) {
#pragma unroll
        for (int nt = 0; nt < 4; nt++) {
            int row = m0 + wm + mt * 16 + (lane >> 2);
            int col = n0 + wn + nt * 8 + (lane & 3) * 2;
            float* a4 = acc[mt][nt];
            if (EPI == 2) {
                __nv_bfloat16* Cb = (__nv_bfloat16*)Cout + (long)bz * sC;
                float s0 = ((a4[0] * 0.125f) / TAUf - 0.5f >= 0.f) ? 1.f : 0.f;
                float s1 = ((a4[1] * 0.125f) / TAUf - 0.5f >= 0.f) ? 1.f : 0.f;
                float s2 = ((a4[2] * 0.125f) / TAUf - 0.5f >= 0.f) ? 1.f : 0.f;
                float s3 = ((a4[3] * 0.125f) / TAUf - 0.5f >= 0.f) ? 1.f : 0.f;
                *(__nv_bfloat162*)&Cb[(long)row * ldc + col] = __floats2bfloat162_rn(s0, s1);
                *(__nv_bfloat162*)&Cb[(long)(row + 8) * ldc + col] = __floats2bfloat162_rn(s2, s3);
            } else {
                float* Cb = (float*)Cout + (long)bz * sC;
                float b0 = (EPI == 1) ? bias[row] : 0.f;
                float b8 = (EPI == 1) ? bias[row + 8] : 0.f;
                *(float2*)&Cb[(long)row * ldc + col] = make_float2(a4[0] + b0, a4[1] + b0);
                *(float2*)&Cb[(long)(row + 8) * ldc + col] = make_float2(a4[2] + b8, a4[3] + b8);
            }
        }
    }
}

// ---------------------------------------------------------------------------
// weight conversion: stack q/k/v weights as bf16; 3-way bf16 split of proj w
// ---------------------------------------------------------------------------
__global__ void __launch_bounds__(256)
convert_weights(const float* __restrict__ qw, const float* __restrict__ kw,
                const float* __restrict__ vw, const float* __restrict__ pw,
                __nv_bfloat16* __restrict__ wqkv, __nv_bfloat16* __restrict__ pw3)
{
    int i = blockIdx.x * 256 + threadIdx.x;   // 512*512
    wqkv[i]                = __float2bfloat16(qw[i]);
    wqkv[i + CC * CC]      = __float2bfloat16(kw[i]);
    wqkv[i + 2 * CC * CC]  = __float2bfloat16(vw[i]);

    int m = i >> 9, k = i & 511;
    float w   = pw[i];
    __nv_bfloat16 hb = __float2bfloat16(w);
    float r1  = w - __bfloat162float(hb);
    __nv_bfloat16 mb = __float2bfloat16(r1);
    float r2  = r1 - __bfloat162float(mb);
    __nv_bfloat16 lb = __float2bfloat16(r2);
    long base = (long)m * (3 * CC) + k;
    pw3[base] = hb; pw3[base + 512] = mb; pw3[base + 1024] = lb;
}

// ---------------------------------------------------------------------------
// x [b][c][n] fp32 -> xT [b][n][c] bf16 (tiled transpose)
// ---------------------------------------------------------------------------
__global__ void __launch_bounds__(256)
xT_kernel(const float* __restrict__ x, __nv_bfloat16* __restrict__ xT)
{
    __shared__ float t[32][33];
    int b = blockIdx.z, n0 = blockIdx.x * 32, c0 = blockIdx.y * 32;
    int tx = threadIdx.x, ty = threadIdx.y;
    const float* xb = x + (long)b * CC * NN;
    __nv_bfloat16* ob = xT + (long)b * NN * CC;
#pragma unroll
    for (int i = 0; i < 32; i += 8)
        t[ty + i][tx] = xb[(long)(c0 + ty + i) * NN + n0 + tx];
    __syncthreads();
#pragma unroll
    for (int i = 0; i < 32; i += 8)
        ob[(long)(n0 + ty + i) * CC + c0 + tx] = __float2bfloat16(t[tx][ty + i]);
}

// ---------------------------------------------------------------------------
// per-channel stats over (B, N); bstride = per-batch element stride
// ---------------------------------------------------------------------------
__global__ void __launch_bounds__(256)
stats_kernel(const float* __restrict__ y, long bstride,
             float* __restrict__ mean_out, float* __restrict__ inv_out)
{
    const int c = blockIdx.x;
    const int tid = threadIdx.x;
    float s = 0.f, s2 = 0.f;
    for (int b = 0; b < BB; b++) {
        const float* p = y + (long)b * bstride + (long)c * NN;
        for (int n = tid; n < NN; n += 256) {
            float v = p[n];
            s += v;
            s2 = fmaf(v, v, s2);
        }
    }
    __shared__ float sh1[8], sh2[8];
#pragma unroll
    for (int o = 16; o > 0; o >>= 1) {
        s  += __shfl_down_sync(0xffffffffu, s,  o);
        s2 += __shfl_down_sync(0xffffffffu, s2, o);
    }
    if ((tid & 31) == 0) { sh1[tid >> 5] = s; sh2[tid >> 5] = s2; }
    __syncthreads();
    if (tid < 32) {
        s  = (tid < 8) ? sh1[tid] : 0.f;
        s2 = (tid < 8) ? sh2[tid] : 0.f;
#pragma unroll
        for (int o = 4; o > 0; o >>= 1) {
            s  += __shfl_down_sync(0xffffffffu, s,  o);
            s2 += __shfl_down_sync(0xffffffffu, s2, o);
        }
        if (tid == 0) {
            const float invn = 1.f / (float)(BB * NN);
            float m = s * invn;
            float var = s2 * invn - m * m;
            mean_out[c] = m;
            inv_out[c] = rsqrtf(var + EPSf);
        }
    }
}

// ---------------------------------------------------------------------------
// q: BN + threshold + transpose -> fp16 qT [b][n][c]
// ---------------------------------------------------------------------------
__global__ void __launch_bounds__(256)
spike_qT_kernel(const float* __restrict__ y, long bstride,
                const float* __restrict__ mean, const float* __restrict__ inv,
                const float* __restrict__ gamma, const float* __restrict__ beta,
                __half* __restrict__ qT)
{
    __shared__ float t[32][33];
    int b = blockIdx.z, n0 = blockIdx.x * 32, c0 = blockIdx.y * 32;
    int tx = threadIdx.x, ty = threadIdx.y;
    const float* yb = y + (long)b * bstride;
#pragma unroll
    for (int i = 0; i < 32; i += 8) {
        int c = c0 + ty + i;
        float v = yb[(long)c * NN + n0 + tx];
        float bn = fmaf(gamma[c] * inv[c], v - mean[c], beta[c]);
        t[ty + i][tx] = (bn / TAUf - 1.0f >= 0.f) ? 1.f : 0.f;
    }
    __syncthreads();
    __half* ob = qT + (long)b * NN * CC;
#pragma unroll
    for (int i = 0; i < 32; i += 8)
        ob[(long)(n0 + ty + i) * CC + c0 + tx] = __float2half(t[tx][ty + i]);
}

// ---------------------------------------------------------------------------
// k/v: BN + threshold -> bitpacked
// ---------------------------------------------------------------------------
__global__ void __launch_bounds__(256)
spike_pack_kernel(const float* __restrict__ y, long bstride,
                  const float* __restrict__ mean, const float* __restrict__ inv,
                  const float* __restrict__ gamma, const float* __restrict__ beta,
                  unsigned* __restrict__ bits)
{
    long i = (long)blockIdx.x * 256 + threadIdx.x;
    int b = (int)(i >> 19);
    long r = i & ((1 << 19) - 1);
    int c = (int)(r >> 10);
    float v = y[(long)b * bstride + r];
    float bn = fmaf(gamma[c] * inv[c], v - mean[c], beta[c]);
    bool spike = (bn / TAUf - 1.0f) >= 0.f;
    unsigned m = __ballot_sync(0xffffffffu, spike);
    if ((threadIdx.x & 31) == 0) bits[i >> 5] = m;
}

// ---------------------------------------------------------------------------
// kvT[b][d][c] = popc over N of k_bits[c] & v_bits[d]  (fp16, exact)
// ---------------------------------------------------------------------------
__global__ void __launch_bounds__(256)
kv_popc_kernel(const unsigned* __restrict__ kb, const unsigned* __restrict__ vb,
               __half* __restrict__ kvT)
{
    __shared__ unsigned ks[32][65];
    __shared__ unsigned vs[32][65];
    const int bz = blockIdx.z;
    const int c0 = blockIdx.y * 64;
    const int d0 = blockIdx.x * 64;
    const unsigned* kbb = kb + (long)bz * CC * (NN / 32);
    const unsigned* vbb = vb + (long)bz * CC * (NN / 32);
    const int tid = threadIdx.x;
#pragma unroll
    for (int it = 0; it < 8; it++) {
        int idx = tid + it * 256;
        int r = idx >> 5, w = idx & 31;
        ks[w][r] = kbb[(long)(c0 + r) * 32 + w];
        vs[w][r] = vbb[(long)(d0 + r) * 32 + w];
    }
    __syncthreads();
    const int tm = (tid >> 4) * 4;   // c
    const int tn = (tid & 15) * 4;   // d
    int cnt[4][4];
#pragma unroll
    for (int i = 0; i < 4; i++)
#pragma unroll
        for (int j = 0; j < 4; j++) cnt[i][j] = 0;
#pragma unroll
    for (int w = 0; w < 32; w++) {
        unsigned a[4], b[4];
#pragma unroll
        for (int i = 0; i < 4; i++) a[i] = ks[w][tm + i];
#pragma unroll
        for (int j = 0; j < 4; j++) b[j] = vs[w][tn + j];
#pragma unroll
        for (int i = 0; i < 4; i++)
#pragma unroll
            for (int j = 0; j < 4; j++)
                cnt[i][j] += __popc(a[i] & b[j]);
    }
    __half* ob = kvT + (long)bz * CC * CC;
#pragma unroll
    for (int j = 0; j < 4; j++) {
        long base = (long)(d0 + tn + j) * CC + c0 + tm;
        __half2 p0 = __halves2half2(__float2half((float)cnt[0][j]),
                                    __float2half((float)cnt[1][j]));
        __half2 p1 = __halves2half2(__float2half((float)cnt[2][j]),
                                    __float2half((float)cnt[3][j]));
        *(__half2*)&ob[base] = p0;
        *(__half2*)&ob[base + 2] = p1;
    }
}

// ---------------------------------------------------------------------------
// attn [b][d][n] bf16 -> attnT [b][n][d] bf16
// ---------------------------------------------------------------------------
__global__ void __launch_bounds__(256)
attnT_kernel(const __nv_bfloat16* __restrict__ a, __nv_bfloat16* __restrict__ at)
{
    __shared__ __nv_bfloat16 t[32][34];
    int b = blockIdx.z, n0 = blockIdx.x * 32, d0 = blockIdx.y * 32;
    int tx = threadIdx.x, ty = threadIdx.y;
    const __nv_bfloat16* ab = a + (long)b * CC * NN;
    __nv_bfloat16* ob = at + (long)b * NN * CC;
#pragma unroll
    for (int i = 0; i < 32; i += 8)
        t[ty + i][tx] = ab[(long)(d0 + ty + i) * NN + n0 + tx];
    __syncthreads();
#pragma unroll
    for (int i = 0; i < 32; i += 8)
        ob[(long)(n0 + ty + i) * CC + d0 + tx] = t[tx][ty + i];
}

// ---------------------------------------------------------------------------
// final BN + LIF -> d_out (fp32), contiguous [b][c][n]
// ---------------------------------------------------------------------------
__global__ void __launch_bounds__(256)
spike_float_kernel(const float* __restrict__ y,
                   const float* __restrict__ mean, const float* __restrict__ inv,
                   const float* __restrict__ gamma, const float* __restrict__ beta,
                   float* __restrict__ out)
{
    long i = (long)blockIdx.x * 256 + threadIdx.x;
    int c = (int)((i >> 10) & (CC - 1));
    float bnv = fmaf(gamma[c] * inv[c], y[i] - mean[c], beta[c]);
    out[i] = (bnv / TAUf - 1.0f >= 0.f) ? 1.f : 0.f;
}

// ---------------------------------------------------------------------------
extern "C" void kernel_launch(void* const* d_in, const int* in_sizes, int n_in,
                              void* d_out, int out_size)
{
    const float* x      = (const float*)d_in[0];
    const float* q_w    = (const float*)d_in[1];
    const float* q_g    = (const float*)d_in[2];
    const float* q_b    = (const float*)d_in[3];
    const float* k_w    = (const float*)d_in[4];
    const float* k_g    = (const float*)d_in[5];
    const float* k_b    = (const float*)d_in[6];
    const float* v_w    = (const float*)d_in[7];
    const float* v_g    = (const float*)d_in[8];
    const float* v_b    = (const float*)d_in[9];
    const float* p_w    = (const float*)d_in[10];
    const float* p_g    = (const float*)d_in[11];
    const float* p_beta = (const float*)d_in[12];
    const float* p_bias = (const float*)d_in[13];

    void* p;
    cudaGetSymbolAddress(&p, g_y);     float*         gy    = (float*)p;
    cudaGetSymbolAddress(&p, g_xT);    __nv_bfloat16* gxT   = (__nv_bfloat16*)p;
    cudaGetSymbolAddress(&p, g_qT);    __half*        gqT   = (__half*)p;
    cudaGetSymbolAddress(&p, g_kbits); unsigned*      gkb   = (unsigned*)p;
    cudaGetSymbolAddress(&p, g_vbits); unsigned*      gvb   = (unsigned*)p;
    cudaGetSymbolAddress(&p, g_kvT);   __half*        gkvT  = (__half*)p;
    cudaGetSymbolAddress(&p, g_attn);  __nv_bfloat16* gatt  = (__nv_bfloat16*)p;
    cudaGetSymbolAddress(&p, g_attnT); __nv_bfloat16* gattT = (__nv_bfloat16*)p;
    cudaGetSymbolAddress(&p, g_proj);  float*         gpr   = (float*)p;
    cudaGetSymbolAddress(&p, g_wqkv);  __nv_bfloat16* gwqkv = (__nv_bfloat16*)p;
    cudaGetSymbolAddress(&p, g_pw3);   __nv_bfloat16* gpw3  = (__nv_bfloat16*)p;
    cudaGetSymbolAddress(&p, g_mean);  float*         gmean = (float*)p;
    cudaGetSymbolAddress(&p, g_inv);   float*         ginv  = (float*)p;

    const long sNC    = (long)NN * CC;       // 524288
    const long sY     = (long)3 * CC * NN;   // per-batch stride of qkv out
    const long sCN    = (long)CC * NN;
    const unsigned nblk = (unsigned)(BCN / 256);
    dim3 t32(32, 8);
    dim3 gT(NN / 32, CC / 32, BB);           // (32, 16, 32)

    // 0) weight conversion + x transpose
    convert_weights<<<(CC * CC) / 256, 256>>>(q_w, k_w, v_w, p_w, gwqkv, gpw3);
    xT_kernel<<<gT, t32>>>(x, gxT);

    // 1) fused qkv conv GEMM: M=1536, N=1024, K=512 (bf16)
    gemm_mma<0, 0><<<dim3(NN / 128, 12, BB), 256>>>(
        (const uint16_t*)gwqkv, CC, 0,
        (const uint16_t*)gxT, CC, sNC, CC,
        gy, NN, sY, 3 * CC, NN, CC, nullptr);

    // 2) stats
    stats_kernel<<<CC, 256>>>(gy,                sY, gmean + 0 * CC, ginv + 0 * CC);
    stats_kernel<<<CC, 256>>>(gy + 1 * CC * NN,  sY, gmean + 1 * CC, ginv + 1 * CC);
    stats_kernel<<<CC, 256>>>(gy + 2 * CC * NN,  sY, gmean + 2 * CC, ginv + 2 * CC);

    // 3) spikes: q -> fp16 transposed, k/v -> bitpacked
    spike_qT_kernel<<<gT, t32>>>(gy, sY, gmean, ginv, q_g, q_b, gqT);
    spike_pack_kernel<<<nblk, 256>>>(gy + 1 * CC * NN, sY,
                                     gmean + 1 * CC, ginv + 1 * CC, k_g, k_b, gkb);
    spike_pack_kernel<<<nblk, 256>>>(gy + 2 * CC * NN, sY,
                                     gmean + 2 * CC, ginv + 2 * CC, v_g, v_b, gvb);

    // 4) kv^T via popcount (fp16, exact)
    kv_popc_kernel<<<dim3(CC / 64, CC / 64, BB), 256>>>(gkb, gvb, gkvT);

    // 5) attn GEMM (fp16, exact) + fused spike epilogue
    gemm_mma<1, 2><<<dim3(NN / 128, CC / 128, BB), 256>>>(
        (const uint16_t*)gkvT, CC, (long)CC * CC,
        (const uint16_t*)gqT, CC, sNC, CC,
        gatt, NN, sCN, CC, NN, CC, nullptr);

    // 6) transpose attn spikes
    attnT_kernel<<<gT, t32>>>(gatt, gattT);

    // 7) proj GEMM: 3-way bf16 split, K=1536 (fp32-accurate) + bias
    gemm_mma<0, 1><<<dim3(NN / 128, CC / 128, BB), 256>>>(
        (const uint16_t*)gpw3, 3 * CC, 0,
        (const uint16_t*)gattT, CC, sNC, CC,
        gpr, NN, sCN, CC, NN, 3 * CC, p_bias);

    // 8) final stats + spike
    stats_kernel<<<CC, 256>>>(gpr, sCN, gmean + 3 * CC, ginv + 3 * CC);
    spike_float_kernel<<<nblk, 256>>>(gpr, gmean + 3 * CC, ginv + 3 * CC,
                                      p_g, p_beta, (float*)d_out);
}

// round 11
// speedup vs baseline: 7.9660x; 1.8055x over previous
#include <cuda_runtime.h>
#include <cuda_bf16.h>
#include <cuda_fp16.h>
#include <cstdint>

// ---------------------------------------------------------------------------
// SSA — B=32, C=512, N=1024. mma.sync tensor-core version, fused BN stats.
//   qkv conv : one bf16 GEMM M=1536 (stacked weights), epilogue: bf16 store +
//              per-channel sum/sumsq atomics
//   finalize -> BN/LIF; q -> fp16 q^T, k/v -> bitpacked
//   kv^T via AND+POPC (exact) -> fp16
//   attn^T   : fp16 GEMM (exact ints) A=q^T B=kv^T, fused spike epilogue
//   proj     : bf16 GEMM K=512, fused bias + stats epilogue (fp32 out)
//   finalize -> BN/LIF -> d_out
// ---------------------------------------------------------------------------

namespace {
constexpr int  BB  = 32;
constexpr int  CC  = 512;
constexpr int  NN  = 1024;
constexpr long BCN = (long)BB * CC * NN;
constexpr long SY  = (long)3 * CC * NN;       // per-batch stride of qkv out
constexpr float TAUf = 1.1f;
constexpr float EPSf = 1e-5f;
}

// scratch (device globals)
__device__ __nv_bfloat16 g_y[BB * 3 * CC * NN];     // qkv conv out (bf16)
__device__ __nv_bfloat16 g_xT[BB * CC * NN];        // x^T [b][n][c]
__device__ __half        g_qT[BB * CC * NN];        // q spikes^T [b][n][c]
__device__ unsigned      g_kbits[BB * CC * NN / 32];
__device__ unsigned      g_vbits[BB * CC * NN / 32];
__device__ __half        g_kvT[BB * CC * CC];       // kv^T [b][d][c]
__device__ __nv_bfloat16 g_attnT[BB * CC * NN];     // attn spikes [b][n][d]
__device__ float         g_proj[BB * CC * NN];      // proj out (fp32)
__device__ __nv_bfloat16 g_wqkv[3 * CC * CC];
__device__ __nv_bfloat16 g_pw[CC * CC];
__device__ float         g_ssum[4 * CC];            // stats partials
__device__ float         g_ssum2[4 * CC];
__device__ float         g_mean[4 * CC];
__device__ float         g_inv[4 * CC];

// ---------------------------------------------------------------------------
__device__ __forceinline__ uint32_t smem_u32(const void* p) {
    return (uint32_t)__cvta_generic_to_shared(p);
}
__device__ __forceinline__ void cp_async16(uint32_t s, const void* g) {
    asm volatile("cp.async.cg.shared.global [%0], [%1], 16;" :: "r"(s), "l"(g));
}
__device__ __forceinline__ void ldm_x4(uint32_t& r0, uint32_t& r1,
                                       uint32_t& r2, uint32_t& r3, uint32_t a) {
    asm volatile("ldmatrix.sync.aligned.m8n8.x4.shared.b16 {%0,%1,%2,%3}, [%4];"
                 : "=r"(r0), "=r"(r1), "=r"(r2), "=r"(r3) : "r"(a));
}
template<int FT>
__device__ __forceinline__ void mma_16816(float* c, const uint32_t* a, const uint32_t* b) {
    if constexpr (FT == 0) {
        asm volatile(
            "mma.sync.aligned.m16n8k16.row.col.f32.bf16.bf16.f32 "
            "{%0,%1,%2,%3},{%4,%5,%6,%7},{%8,%9},{%0,%1,%2,%3};"
            : "+f"(c[0]), "+f"(c[1]), "+f"(c[2]), "+f"(c[3])
            : "r"(a[0]), "r"(a[1]), "r"(a[2]), "r"(a[3]), "r"(b[0]), "r"(b[1]));
    } else {
        asm volatile(
            "mma.sync.aligned.m16n8k16.row.col.f32.f16.f16.f32 "
            "{%0,%1,%2,%3},{%4,%5,%6,%7},{%8,%9},{%0,%1,%2,%3};"
            : "+f"(c[0]), "+f"(c[1]), "+f"(c[2]), "+f"(c[3])
            : "r"(a[0]), "r"(a[1]), "r"(a[2]), "r"(a[3]), "r"(b[0]), "r"(b[1]));
    }
}

// ---------------------------------------------------------------------------
// GEMM: C[m,n] = sum_k A[m][k] * BT[n][k]
//   FT: 0 bf16, 1 fp16
//   EPI: 0 = bf16 store + stats, 1 = f32 store + bias + stats, 2 = bf16 spike
// CTA tile 128x128, K-step 32, 8 warps (64x32 per warp), double-buffered.
// ---------------------------------------------------------------------------
template<int FT, int EPI>
__global__ void __launch_bounds__(256)
gemm_mma(const uint16_t* __restrict__ A, int lda, long sA,
         const uint16_t* __restrict__ BT, int ldb, long sB,
         void* __restrict__ Cout, int ldc, long sC,
         int M, int Nn, int K,
         const float* __restrict__ bias,
         float* __restrict__ ssum, float* __restrict__ ssum2)
{
    constexpr int LDS = 40;
    __shared__ uint16_t As[2][128 * LDS];
    __shared__ uint16_t Bs[2][128 * LDS];

    const int bz = blockIdx.z;
    const uint16_t* Ab = A + (long)bz * sA;
    const uint16_t* Bb = BT + (long)bz * sB;
    const int m0 = blockIdx.y * 128, n0 = blockIdx.x * 128;
    const int tid = threadIdx.x;
    const int lane = tid & 31, warp = tid >> 5;
    const int wm = (warp & 1) * 64, wn = (warp >> 1) * 32;

    float acc[4][4][4];
#pragma unroll
    for (int i = 0; i < 4; i++)
#pragma unroll
        for (int j = 0; j < 4; j++)
#pragma unroll
            for (int r = 0; r < 4; r++) acc[i][j][r] = 0.f;

    auto issue = [&](int st, int k0) {
#pragma unroll
        for (int i = 0; i < 2; i++) {
            int c = tid + i * 256;
            int row = c >> 2, kc = (c & 3) << 3;
            cp_async16(smem_u32(&As[st][row * LDS + kc]),
                       Ab + (long)(m0 + row) * lda + k0 + kc);
            cp_async16(smem_u32(&Bs[st][row * LDS + kc]),
                       Bb + (long)(n0 + row) * ldb + k0 + kc);
        }
        asm volatile("cp.async.commit_group;");
    };

    const int KT = K / 32;
    issue(0, 0);
    for (int kt = 0; kt < KT; kt++) {
        if (kt + 1 < KT) {
            issue((kt + 1) & 1, (kt + 1) * 32);
            asm volatile("cp.async.wait_group 1;");
        } else {
            asm volatile("cp.async.wait_group 0;");
        }
        __syncthreads();
        const uint16_t* as = As[kt & 1];
        const uint16_t* bs = Bs[kt & 1];
#pragma unroll
        for (int kk = 0; kk < 2; kk++) {
            uint32_t af[4][4], bf[4][2];
#pragma unroll
            for (int mt = 0; mt < 4; mt++) {
                int row = wm + mt * 16 + (lane & 15);
                int kcol = kk * 16 + (lane >> 4) * 8;
                ldm_x4(af[mt][0], af[mt][1], af[mt][2], af[mt][3],
                       smem_u32(&as[row * LDS + kcol]));
            }
#pragma unroll
            for (int p = 0; p < 2; p++) {
                int g = lane >> 3;
                int row = wn + p * 16 + (g >> 1) * 8 + (lane & 7);
                int kcol = kk * 16 + (g & 1) * 8;
                uint32_t r0, r1, r2, r3;
                ldm_x4(r0, r1, r2, r3, smem_u32(&bs[row * LDS + kcol]));
                bf[p * 2][0] = r0; bf[p * 2][1] = r1;
                bf[p * 2 + 1][0] = r2; bf[p * 2 + 1][1] = r3;
            }
#pragma unroll
            for (int mt = 0; mt < 4; mt++)
#pragma unroll
                for (int nt = 0; nt < 4; nt++)
                    mma_16816<FT>(acc[mt][nt], af[mt], bf[nt]);
        }
        __syncthreads();
    }

    // epilogue
#pragma unroll
    for (int mt = 0; mt < 4; mt++) {
        int row = m0 + wm + mt * 16 + (lane >> 2);
        float b0 = 0.f, b8 = 0.f;
        if (EPI == 1) { b0 = bias[row]; b8 = bias[row + 8]; }
        float sl = 0.f, ql = 0.f, sh = 0.f, qh = 0.f;
#pragma unroll
        for (int nt = 0; nt < 4; nt++) {
            int col = n0 + wn + nt * 8 + (lane & 3) * 2;
            float* a4 = acc[mt][nt];
            if (EPI == 2) {
                __nv_bfloat16* Cb = (__nv_bfloat16*)Cout + (long)bz * sC;
                float s0 = ((a4[0] * 0.125f) / TAUf - 0.5f >= 0.f) ? 1.f : 0.f;
                float s1 = ((a4[1] * 0.125f) / TAUf - 0.5f >= 0.f) ? 1.f : 0.f;
                float s2 = ((a4[2] * 0.125f) / TAUf - 0.5f >= 0.f) ? 1.f : 0.f;
                float s3 = ((a4[3] * 0.125f) / TAUf - 0.5f >= 0.f) ? 1.f : 0.f;
                *(__nv_bfloat162*)&Cb[(long)row * ldc + col] = __floats2bfloat162_rn(s0, s1);
                *(__nv_bfloat162*)&Cb[(long)(row + 8) * ldc + col] = __floats2bfloat162_rn(s2, s3);
            } else if (EPI == 0) {
                __nv_bfloat16* Cb = (__nv_bfloat16*)Cout + (long)bz * sC;
                float v0 = a4[0], v1 = a4[1], v2 = a4[2], v3 = a4[3];
                *(__nv_bfloat162*)&Cb[(long)row * ldc + col] = __floats2bfloat162_rn(v0, v1);
                *(__nv_bfloat162*)&Cb[(long)(row + 8) * ldc + col] = __floats2bfloat162_rn(v2, v3);
                sl += v0 + v1; ql = fmaf(v0, v0, fmaf(v1, v1, ql));
                sh += v2 + v3; qh = fmaf(v2, v2, fmaf(v3, v3, qh));
            } else {
                float* Cb = (float*)Cout + (long)bz * sC;
                float v0 = a4[0] + b0, v1 = a4[1] + b0;
                float v2 = a4[2] + b8, v3 = a4[3] + b8;
                *(float2*)&Cb[(long)row * ldc + col] = make_float2(v0, v1);
                *(float2*)&Cb[(long)(row + 8) * ldc + col] = make_float2(v2, v3);
                sl += v0 + v1; ql = fmaf(v0, v0, fmaf(v1, v1, ql));
                sh += v2 + v3; qh = fmaf(v2, v2, fmaf(v3, v3, qh));
            }
        }
        if (EPI != 2) {
            sl += __shfl_xor_sync(0xffffffffu, sl, 1);
            sl += __shfl_xor_sync(0xffffffffu, sl, 2);
            ql += __shfl_xor_sync(0xffffffffu, ql, 1);
            ql += __shfl_xor_sync(0xffffffffu, ql, 2);
            sh += __shfl_xor_sync(0xffffffffu, sh, 1);
            sh += __shfl_xor_sync(0xffffffffu, sh, 2);
            qh += __shfl_xor_sync(0xffffffffu, qh, 1);
            qh += __shfl_xor_sync(0xffffffffu, qh, 2);
            if ((lane & 3) == 0) {
                atomicAdd(&ssum[row], sl);  atomicAdd(&ssum2[row], ql);
                atomicAdd(&ssum[row + 8], sh); atomicAdd(&ssum2[row + 8], qh);
            }
        }
    }
}

// ---------------------------------------------------------------------------
__global__ void __launch_bounds__(256)
zero_stats(float* __restrict__ a, float* __restrict__ b)
{
    int i = blockIdx.x * 256 + threadIdx.x;
    if (i < 4 * CC) { a[i] = 0.f; b[i] = 0.f; }
}

__global__ void __launch_bounds__(256)
finalize_stats(const float* __restrict__ ss, const float* __restrict__ ss2,
               float* __restrict__ mean, float* __restrict__ inv, int nch)
{
    int i = blockIdx.x * 256 + threadIdx.x;
    if (i < nch) {
        const float invn = 1.f / (float)(BB * NN);
        float m = ss[i] * invn;
        float var = ss2[i] * invn - m * m;
        mean[i] = m;
        inv[i] = rsqrtf(var + EPSf);
    }
}

// ---------------------------------------------------------------------------
// weight conversion
// ---------------------------------------------------------------------------
__global__ void __launch_bounds__(256)
convert_weights(const float* __restrict__ qw, const float* __restrict__ kw,
                const float* __restrict__ vw, const float* __restrict__ pw,
                __nv_bfloat16* __restrict__ wqkv, __nv_bfloat16* __restrict__ pwo)
{
    int i = blockIdx.x * 256 + threadIdx.x;
    wqkv[i]               = __float2bfloat16(qw[i]);
    wqkv[i + CC * CC]     = __float2bfloat16(kw[i]);
    wqkv[i + 2 * CC * CC] = __float2bfloat16(vw[i]);
    pwo[i]                = __float2bfloat16(pw[i]);
}

// ---------------------------------------------------------------------------
// x [b][c][n] fp32 -> xT [b][n][c] bf16
// ---------------------------------------------------------------------------
__global__ void __launch_bounds__(256)
xT_kernel(const float* __restrict__ x, __nv_bfloat16* __restrict__ xT)
{
    __shared__ float t[32][33];
    int b = blockIdx.z, n0 = blockIdx.x * 32, c0 = blockIdx.y * 32;
    int tx = threadIdx.x, ty = threadIdx.y;
    const float* xb = x + (long)b * CC * NN;
    __nv_bfloat16* ob = xT + (long)b * NN * CC;
#pragma unroll
    for (int i = 0; i < 32; i += 8)
        t[ty + i][tx] = xb[(long)(c0 + ty + i) * NN + n0 + tx];
    __syncthreads();
#pragma unroll
    for (int i = 0; i < 32; i += 8)
        ob[(long)(n0 + ty + i) * CC + c0 + tx] = __float2bfloat16(t[tx][ty + i]);
}

// ---------------------------------------------------------------------------
// q: BN + threshold + transpose -> fp16 qT [b][n][c]   (y is bf16)
// ---------------------------------------------------------------------------
__global__ void __launch_bounds__(256)
spike_qT_kernel(const __nv_bfloat16* __restrict__ y, long bstride,
                const float* __restrict__ mean, const float* __restrict__ inv,
                __half* __restrict__ qT)
{
    __shared__ float t[32][33];
    int b = blockIdx.z, n0 = blockIdx.x * 32, c0 = blockIdx.y * 32;
    int tx = threadIdx.x, ty = threadIdx.y;
    const __nv_bfloat16* yb = y + (long)b * bstride;
#pragma unroll
    for (int i = 0; i < 32; i += 8) {
        int c = c0 + ty + i;
        float v = __bfloat162float(yb[(long)c * NN + n0 + tx]);
        float bn = inv[c] * (v - mean[c]);     // gamma=1, beta=0 semantics handled by caller arrays
        t[ty + i][tx] = (bn / TAUf - 1.0f >= 0.f) ? 1.f : 0.f;
    }
    __syncthreads();
    __half* ob = qT + (long)b * NN * CC;
#pragma unroll
    for (int i = 0; i < 32; i += 8)
        ob[(long)(n0 + ty + i) * CC + c0 + tx] = __float2half(t[tx][ty + i]);
}

// ---------------------------------------------------------------------------
// k/v: BN + threshold -> bitpacked (4 elems/thread, warp-permuted bit layout;
// layout identical for k and v so AND+POPC dot products are unaffected)
// ---------------------------------------------------------------------------
__global__ void __launch_bounds__(256)
spike_pack_kernel(const __nv_bfloat16* __restrict__ y, long bstride,
                  const float* __restrict__ mean, const float* __restrict__ inv,
                  unsigned* __restrict__ bits)
{
    long t = (long)blockIdx.x * 256 + threadIdx.x;   // BCN/4 threads
    long e = t * 4;
    int b = (int)(e / ((long)CC * NN));
    long r = e - (long)b * CC * NN;
    int c = (int)(r >> 10);
    const __nv_bfloat16* p = y + (long)b * bstride + r;
    uint2 raw = *(const uint2*)p;
    __nv_bfloat162 p01 = *(__nv_bfloat162*)&raw.x;
    __nv_bfloat162 p23 = *(__nv_bfloat162*)&raw.y;
    float g = inv[c], m = mean[c];
    float v0 = __low2float(p01), v1 = __high2float(p01);
    float v2 = __low2float(p23), v3 = __high2float(p23);
    unsigned m0 = __ballot_sync(0xffffffffu, (g * (v0 - m)) / TAUf - 1.f >= 0.f);
    unsigned m1 = __ballot_sync(0xffffffffu, (g * (v1 - m)) / TAUf - 1.f >= 0.f);
    unsigned m2 = __ballot_sync(0xffffffffu, (g * (v2 - m)) / TAUf - 1.f >= 0.f);
    unsigned m3 = __ballot_sync(0xffffffffu, (g * (v3 - m)) / TAUf - 1.f >= 0.f);
    int lane = threadIdx.x & 31;
    long e0 = e - (long)lane * 4;                    // warp's first element
    unsigned w = (lane == 0) ? m0 : (lane == 1) ? m1 : (lane == 2) ? m2 : m3;
    if (lane < 4) bits[(e0 >> 5) + lane] = w;
}

// ---------------------------------------------------------------------------
// kvT[b][d][c] = popc over N of k_bits[c] & v_bits[d]  (fp16, exact)
// ---------------------------------------------------------------------------
__global__ void __launch_bounds__(256)
kv_popc_kernel(const unsigned* __restrict__ kb, const unsigned* __restrict__ vb,
               __half* __restrict__ kvT)
{
    __shared__ unsigned ks[32][65];
    __shared__ unsigned vs[32][65];
    const int bz = blockIdx.z;
    const int c0 = blockIdx.y * 64;
    const int d0 = blockIdx.x * 64;
    const unsigned* kbb = kb + (long)bz * CC * (NN / 32);
    const unsigned* vbb = vb + (long)bz * CC * (NN / 32);
    const int tid = threadIdx.x;
#pragma unroll
    for (int it = 0; it < 8; it++) {
        int idx = tid + it * 256;
        int r = idx >> 5, w = idx & 31;
        ks[w][r] = kbb[(long)(c0 + r) * 32 + w];
        vs[w][r] = vbb[(long)(d0 + r) * 32 + w];
    }
    __syncthreads();
    const int tm = (tid >> 4) * 4;   // c
    const int tn = (tid & 15) * 4;   // d
    int cnt[4][4];
#pragma unroll
    for (int i = 0; i < 4; i++)
#pragma unroll
        for (int j = 0; j < 4; j++) cnt[i][j] = 0;
#pragma unroll
    for (int w = 0; w < 32; w++) {
        unsigned a[4], b[4];
#pragma unroll
        for (int i = 0; i < 4; i++) a[i] = ks[w][tm + i];
#pragma unroll
        for (int j = 0; j < 4; j++) b[j] = vs[w][tn + j];
#pragma unroll
        for (int i = 0; i < 4; i++)
#pragma unroll
            for (int j = 0; j < 4; j++)
                cnt[i][j] += __popc(a[i] & b[j]);
    }
    __half* ob = kvT + (long)bz * CC * CC;
#pragma unroll
    for (int j = 0; j < 4; j++) {
        long base = (long)(d0 + tn + j) * CC + c0 + tm;
        __half2 p0 = __halves2half2(__float2half((float)cnt[0][j]),
                                    __float2half((float)cnt[1][j]));
        __half2 p1 = __halves2half2(__float2half((float)cnt[2][j]),
                                    __float2half((float)cnt[3][j]));
        *(__half2*)&ob[base] = p0;
        *(__half2*)&ob[base + 2] = p1;
    }
}

// ---------------------------------------------------------------------------
// final BN + LIF -> d_out (fp32), vectorized
// ---------------------------------------------------------------------------
__global__ void __launch_bounds__(256)
spike_final_kernel(const float* __restrict__ y,
                   const float* __restrict__ mean, const float* __restrict__ inv,
                   float* __restrict__ out)
{
    long t = (long)blockIdx.x * 256 + threadIdx.x;
    long e = t * 4;
    int c = (int)((e >> 10) & (CC - 1));
    float g = inv[c], m = mean[c];
    float4 v = *(const float4*)&y[e];
    float4 o;
    o.x = ((g * (v.x - m)) / TAUf - 1.f >= 0.f) ? 1.f : 0.f;
    o.y = ((g * (v.y - m)) / TAUf - 1.f >= 0.f) ? 1.f : 0.f;
    o.z = ((g * (v.z - m)) / TAUf - 1.f >= 0.f) ? 1.f : 0.f;
    o.w = ((g * (v.w - m)) / TAUf - 1.f >= 0.f) ? 1.f : 0.f;
    *(float4*)&out[e] = o;
}

// ---------------------------------------------------------------------------
// fold gamma/beta into mean/inv:  bn = gamma*inv*(y-mean) + beta
//   = geff*(y - meff)  with geff = gamma*inv, meff = mean - beta/geff
// (gamma=1, beta=0 here per setup, but handle generally)
// ---------------------------------------------------------------------------
__global__ void __launch_bounds__(256)
fold_affine(float* __restrict__ mean, float* __restrict__ inv,
            const float* __restrict__ gamma, const float* __restrict__ beta, int nch)
{
    int i = blockIdx.x * 256 + threadIdx.x;
    if (i < nch) {
        float g = gamma[i] * inv[i];
        float m = mean[i];
        // bn = g*(y-m)+beta = g*(y - (m - beta/g))   (g != 0 for BN)
        mean[i] = m - beta[i] / g;
        inv[i] = g;
    }
}

// ---------------------------------------------------------------------------
extern "C" void kernel_launch(void* const* d_in, const int* in_sizes, int n_in,
                              void* d_out, int out_size)
{
    const float* x      = (const float*)d_in[0];
    const float* q_w    = (const float*)d_in[1];
    const float* q_g    = (const float*)d_in[2];
    const float* q_b    = (const float*)d_in[3];
    const float* k_w    = (const float*)d_in[4];
    const float* k_g    = (const float*)d_in[5];
    const float* k_b    = (const float*)d_in[6];
    const float* v_w    = (const float*)d_in[7];
    const float* v_g    = (const float*)d_in[8];
    const float* v_b    = (const float*)d_in[9];
    const float* p_w    = (const float*)d_in[10];
    const float* p_g    = (const float*)d_in[11];
    const float* p_beta = (const float*)d_in[12];
    const float* p_bias = (const float*)d_in[13];

    void* p;
    cudaGetSymbolAddress(&p, g_y);     __nv_bfloat16* gy    = (__nv_bfloat16*)p;
    cudaGetSymbolAddress(&p, g_xT);    __nv_bfloat16* gxT   = (__nv_bfloat16*)p;
    cudaGetSymbolAddress(&p, g_qT);    __half*        gqT   = (__half*)p;
    cudaGetSymbolAddress(&p, g_kbits); unsigned*      gkb   = (unsigned*)p;
    cudaGetSymbolAddress(&p, g_vbits); unsigned*      gvb   = (unsigned*)p;
    cudaGetSymbolAddress(&p, g_kvT);   __half*        gkvT  = (__half*)p;
    cudaGetSymbolAddress(&p, g_attnT); __nv_bfloat16* gattT = (__nv_bfloat16*)p;
    cudaGetSymbolAddress(&p, g_proj);  float*         gpr   = (float*)p;
    cudaGetSymbolAddress(&p, g_wqkv);  __nv_bfloat16* gwqkv = (__nv_bfloat16*)p;
    cudaGetSymbolAddress(&p, g_pw);    __nv_bfloat16* gpw   = (__nv_bfloat16*)p;
    cudaGetSymbolAddress(&p, g_ssum);  float*         gss   = (float*)p;
    cudaGetSymbolAddress(&p, g_ssum2); float*         gss2  = (float*)p;
    cudaGetSymbolAddress(&p, g_mean);  float*         gmean = (float*)p;
    cudaGetSymbolAddress(&p, g_inv);   float*         ginv  = (float*)p;

    const long sNC = (long)NN * CC;
    const long sCN = (long)CC * NN;
    dim3 t32(32, 8);
    dim3 gT(NN / 32, CC / 32, BB);

    // 0) zero stats, weight conversion, x transpose
    zero_stats<<<8, 256>>>(gss, gss2);
    convert_weights<<<(CC * CC) / 256, 256>>>(q_w, k_w, v_w, p_w, gwqkv, gpw);
    xT_kernel<<<gT, t32>>>(x, gxT);

    // 1) fused qkv conv GEMM (bf16 out + stats): M=1536, N=1024, K=512
    gemm_mma<0, 0><<<dim3(NN / 128, 12, BB), 256>>>(
        (const uint16_t*)gwqkv, CC, 0,
        (const uint16_t*)gxT, CC, sNC,
        gy, NN, SY, 3 * CC, NN, CC, nullptr, gss, gss2);

    // 2) finalize qkv stats + fold affine params
    finalize_stats<<<6, 256>>>(gss, gss2, gmean, ginv, 3 * CC);
    fold_affine<<<2, 256>>>(gmean + 0 * CC, ginv + 0 * CC, q_g, q_b, CC);
    fold_affine<<<2, 256>>>(gmean + 1 * CC, ginv + 1 * CC, k_g, k_b, CC);
    fold_affine<<<2, 256>>>(gmean + 2 * CC, ginv + 2 * CC, v_g, v_b, CC);

    // 3) spikes: q -> fp16 transposed, k/v -> bitpacked
    spike_qT_kernel<<<gT, t32>>>(gy, SY, gmean, ginv, gqT);
    const unsigned nblk4 = (unsigned)(BCN / 4 / 256);
    spike_pack_kernel<<<nblk4, 256>>>(gy + 1 * sCN, SY, gmean + 1 * CC, ginv + 1 * CC, gkb);
    spike_pack_kernel<<<nblk4, 256>>>(gy + 2 * sCN, SY, gmean + 2 * CC, ginv + 2 * CC, gvb);

    // 4) kv^T via popcount (fp16, exact)
    kv_popc_kernel<<<dim3(CC / 64, CC / 64, BB), 256>>>(gkb, gvb, gkvT);

    // 5) attn^T GEMM (fp16, exact) + fused spike epilogue: M=1024, N=512, K=512
    gemm_mma<1, 2><<<dim3(CC / 128, NN / 128, BB), 256>>>(
        (const uint16_t*)gqT, CC, sNC,
        (const uint16_t*)gkvT, CC, (long)CC * CC,
        gattT, CC, sNC, NN, CC, CC, nullptr, nullptr, nullptr);

    // 6) proj GEMM (bf16) + fused bias + stats: M=512, N=1024, K=512
    gemm_mma<0, 1><<<dim3(NN / 128, CC / 128, BB), 256>>>(
        (const uint16_t*)gpw, CC, 0,
        (const uint16_t*)gattT, CC, sNC,
        gpr, NN, sCN, CC, NN, CC, p_bias, gss + 3 * CC, gss2 + 3 * CC);

    // 7) finalize proj stats + final spike -> d_out
    finalize_stats<<<2, 256>>>(gss + 3 * CC, gss2 + 3 * CC,
                               gmean + 3 * CC, ginv + 3 * CC, CC);
    fold_affine<<<2, 256>>>(gmean + 3 * CC, ginv + 3 * CC, p_g, p_beta, CC);
    spike_final_kernel<<<nblk4, 256>>>(gpr, gmean + 3 * CC, ginv + 3 * CC,
                                       (float*)d_out);
}